// round 12
// baseline (speedup 1.0000x reference)
#include <cuda_runtime.h>
#include <math.h>
#include <stdint.h>

// Problem constants
#define BB 2
#define CC 128
#define HH 64
#define WW 64
#define NH 4
#define DH 32
#define KS 7
#define TOKENS (BB*HH*WW)   // 8192

// Attention tile config
#define TI 8
#define TJ 4
#define NROW 14
#define NCOL 10
#define NPIX (NROW*NCOL)    // 140
#define SKV 36              // Q/K/V smem stride (float4-aligned, 4 mod 32)
#define SWS 72              // weight smem stride (8 mod 32 -> 4-pixel bcast ok)

// Scratch (device globals: no allocation allowed)
__device__ float g_y[TOKENS*CC];
__device__ float g_qkv[TOKENS*3*CC];
__device__ float g_att[TOKENS*CC];
__device__ float g_wq[2*384*128];   // tf32-rounded qkv weights
__device__ float g_wp[2*128*128];   // tf32-rounded proj weights

__device__ __forceinline__ uint32_t f2tf32(float x)
{
    uint32_t r;
    asm("cvt.rna.tf32.f32 %0, %1;" : "=r"(r) : "f"(x));
    return r;
}

__device__ __forceinline__ void mma_tf32(float* d, const uint32_t* a, const uint32_t* b)
{
    asm volatile("mma.sync.aligned.m16n8k8.row.col.f32.tf32.tf32.f32 "
        "{%0,%1,%2,%3}, {%4,%5,%6,%7}, {%8,%9}, {%0,%1,%2,%3};"
        : "+f"(d[0]), "+f"(d[1]), "+f"(d[2]), "+f"(d[3])
        : "r"(a[0]), "r"(a[1]), "r"(a[2]), "r"(a[3]), "r"(b[0]), "r"(b[1]));
}

// ---------------------------------------------------------------------------
// One-shot weight conversion fp32 -> tf32 bit pattern
// ---------------------------------------------------------------------------
__global__ void cvt_w_kernel(const float* __restrict__ qkv_w,
                             const float* __restrict__ proj_w,
                             float* __restrict__ wq,
                             float* __restrict__ wp)
{
    int idx = blockIdx.x * blockDim.x + threadIdx.x;
    const int NQ = 2*384*128;
    const int NP = 2*128*128;
    if (idx < NQ)
        wq[idx] = __uint_as_float(f2tf32(qkv_w[idx]));
    else if (idx < NQ + NP)
        wp[idx - NQ] = __uint_as_float(f2tf32(proj_w[idx - NQ]));
}

// ---------------------------------------------------------------------------
// NCHW -> NHWC transpose
// ---------------------------------------------------------------------------
__global__ void transpose_in_kernel(const float* __restrict__ x, float* __restrict__ y)
{
    __shared__ float tile[32][33];
    int b   = blockIdx.z;
    int hw0 = blockIdx.x * 32;
    int c0  = blockIdx.y * 32;
    int tx = threadIdx.x, ty = threadIdx.y;
    #pragma unroll
    for (int k = 0; k < 32; k += 8)
        tile[ty + k][tx] = x[((b*CC + c0 + ty + k) * (HH*WW)) + hw0 + tx];
    __syncthreads();
    #pragma unroll
    for (int k = 0; k < 32; k += 8)
        y[(b*(HH*WW) + hw0 + ty + k)*CC + c0 + tx] = tile[tx][ty + k];
}

// ---------------------------------------------------------------------------
// tf32 tensor-core GEMM, single-stage full-K smem. (unchanged)
// ---------------------------------------------------------------------------
#define SK 132

__global__ __launch_bounds__(256) void gemm_tc_kernel(
    const float* __restrict__ A,
    const float* __restrict__ W,      // tf32 bits
    const float* __restrict__ bias,
    float* __restrict__ C,
    int N, int scale_q)
{
    extern __shared__ uint32_t smg[];
    uint32_t* As = smg;
    uint32_t* Bs = smg + 64*SK;

    int m0 = blockIdx.x * 64;
    int n0 = blockIdx.y * 64;
    int tid  = threadIdx.x;
    int lane = tid & 31;
    int wid  = tid >> 5;
    int wm = wid & 1;
    int wn = wid >> 1;
    int gp = lane >> 2;
    int tg = lane & 3;

    const float* Ag = A + (m0 + wid)*128 + lane*4;
    const float* Wg = W + (n0 + wid)*128 + lane*4;
    #pragma unroll
    for (int s = 0; s < 8; s++) {
        float4 a = *(const float4*)(Ag + s*8*128);
        float4 b = *(const float4*)(Wg + s*8*128);
        uint4 ua = make_uint4(f2tf32(a.x), f2tf32(a.y), f2tf32(a.z), f2tf32(a.w));
        uint4 ub = make_uint4(__float_as_uint(b.x), __float_as_uint(b.y),
                              __float_as_uint(b.z), __float_as_uint(b.w));
        *(uint4*)&As[(wid + s*8)*SK + lane*4] = ua;
        *(uint4*)&Bs[(wid + s*8)*SK + lane*4] = ub;
    }
    __syncthreads();

    float acc[2][2][4];
    #pragma unroll
    for (int mt = 0; mt < 2; mt++)
        #pragma unroll
        for (int nt = 0; nt < 2; nt++)
            #pragma unroll
            for (int c = 0; c < 4; c++) acc[mt][nt][c] = 0.f;

    #pragma unroll
    for (int ks = 0; ks < 16; ks++) {
        int kb = ks*8;
        uint32_t af[2][4], bf[2][2];
        #pragma unroll
        for (int mt = 0; mt < 2; mt++) {
            int r = wm*32 + mt*16 + gp;
            af[mt][0] = As[r*SK     + kb + tg    ];
            af[mt][1] = As[(r+8)*SK + kb + tg    ];
            af[mt][2] = As[r*SK     + kb + tg + 4];
            af[mt][3] = As[(r+8)*SK + kb + tg + 4];
        }
        #pragma unroll
        for (int nt = 0; nt < 2; nt++) {
            int c = wn*16 + nt*8 + gp;
            bf[nt][0] = Bs[c*SK + kb + tg    ];
            bf[nt][1] = Bs[c*SK + kb + tg + 4];
        }
        #pragma unroll
        for (int mt = 0; mt < 2; mt++)
            #pragma unroll
            for (int nt = 0; nt < 2; nt++)
                mma_tf32(acc[mt][nt], af[mt], bf[nt]);
    }

    const float qs = 0.17677669529663687f;
    #pragma unroll
    for (int mt = 0; mt < 2; mt++) {
        int rbase = m0 + wm*32 + mt*16 + gp;
        #pragma unroll
        for (int nt = 0; nt < 2; nt++) {
            int col = n0 + wn*16 + nt*8 + 2*tg;
            float b0 = bias[col], b1 = bias[col + 1];
            float sc = (scale_q && col < 128) ? qs : 1.f;
            float2 v0 = make_float2((acc[mt][nt][0] + b0)*sc, (acc[mt][nt][1] + b1)*sc);
            float2 v1 = make_float2((acc[mt][nt][2] + b0)*sc, (acc[mt][nt][3] + b1)*sc);
            *(float2*)&C[rbase*N + col]       = v0;
            *(float2*)&C[(rbase + 8)*N + col] = v1;
        }
    }
}
#define GEMM_SMEM (2*64*SK*4)

// ---------------------------------------------------------------------------
// Scalar neighborhood attention v4.
// Block = (head, 8x4 pixel tile), 256 threads, warp w -> pixel row i0+w.
// QK: lane = neighbor, 4 pixels in one t-loop (8 independent FMA chains),
//     softmax butterflies 4-way ILP.
// Weights scattered zero-padded in absolute staged coords Ws[pix][p*10+col].
// AV: warp sweeps the 70-cell union once; V LDS.128 address is lane-group
//     invariant (128B/cell), weight broadcast; lane = (pixel, 4-ch group).
// ---------------------------------------------------------------------------
#define ATTN_SMEM ((32*SKV + 2*NPIX*SKV + 32*SWS + 176)*4)

__global__ __launch_bounds__(256) void attn_kernel(
    const float* __restrict__ qkv,
    const float* __restrict__ rpb,
    float* __restrict__ out)
{
    extern __shared__ float sma[];
    float* Qs = sma;                    // [32][SKV]
    float* Ks = Qs + 32*SKV;            // [NPIX][SKV]
    float* Vs = Ks + NPIX*SKV;          // [NPIX][SKV]
    float* Ws = Vs + NPIX*SKV;          // [32][SWS]  zero-padded weights
    float* rpb_s = Ws + 32*SWS;         // [169]

    int j0 = blockIdx.x * TJ;
    int i0 = blockIdx.y * TI;
    int bh = blockIdx.z;
    int b  = bh >> 2;
    int h  = bh & 3;

    int tid  = threadIdx.x;
    int wid  = tid >> 5;
    int lane = tid & 31;

    int rbase = i0 - 3; rbase = rbase < 0 ? 0 : (rbase > HH-NROW ? HH-NROW : rbase);
    int cbase = j0 - 3; cbase = cbase < 0 ? 0 : (cbase > WW-NCOL ? WW-NCOL : cbase);

    // ---- stage Q, K, V, rpb; zero Ws ----
    for (int pix = wid; pix < 32; pix += 8) {
        int i = i0 + (pix >> 2), j = j0 + (pix & 3);
        Qs[pix*SKV + lane] = qkv[((b*HH + i)*WW + j)*384 + h*DH + lane];
    }
    {
        int gi = 0, gj = wid;   // wid < 8 < NCOL
        for (int r = wid; r < NPIX; r += 8) {
            const float* base = qkv + (((b*HH + rbase + gi)*WW) + cbase + gj)*384 + h*DH;
            Ks[r*SKV + lane] = base[128 + lane];
            Vs[r*SKV + lane] = base[256 + lane];
            gj += 8; if (gj >= NCOL) { gj -= NCOL; gi++; }
        }
    }
    for (int idx = tid; idx < 32*SWS; idx += 256) Ws[idx] = 0.f;
    if (tid < 169) rpb_s[tid] = rpb[h*169 + tid];
    __syncthreads();

    int i  = i0 + wid;
    int si = i - 3; si = si < 0 ? 0 : (si > HH-KS ? HH-KS : si);
    int rb = si - rbase;
    int di = i - si;

    // lane's two window neighbors
    int p0 = lane / KS, c0 = lane % KS;
    int n1 = lane + 32; if (n1 > 48) n1 = 48;
    int p1 = n1 / KS, c1 = n1 % KS;

    // per-pixel column bases
    int cb[TJ], dj[TJ];
    #pragma unroll
    for (int lj = 0; lj < TJ; lj++) {
        int j  = j0 + lj;
        int sj = j - 3; sj = sj < 0 ? 0 : (sj > WW-KS ? WW-KS : sj);
        cb[lj] = sj - cbase;
        dj[lj] = j - sj;
    }

    // ---- QK: 4 pixels simultaneously (8 FMA chains) ----
    float s0[TJ], s1[TJ];
    {
        const float4* qp[TJ];
        const float4* k0p[TJ];
        const float4* k1p[TJ];
        #pragma unroll
        for (int lj = 0; lj < TJ; lj++) {
            qp[lj]  = (const float4*)&Qs[(wid*4 + lj)*SKV];
            k0p[lj] = (const float4*)&Ks[((rb + p0)*NCOL + cb[lj] + c0)*SKV];
            k1p[lj] = (const float4*)&Ks[((rb + p1)*NCOL + cb[lj] + c1)*SKV];
            s0[lj] = 0.f; s1[lj] = 0.f;
        }
        #pragma unroll
        for (int t = 0; t < 8; t++) {
            #pragma unroll
            for (int lj = 0; lj < TJ; lj++) {
                float4 q = qp[lj][t];
                float4 a = k0p[lj][t];
                float4 c = k1p[lj][t];
                s0[lj] = fmaf(q.x, a.x, fmaf(q.y, a.y, fmaf(q.z, a.z, fmaf(q.w, a.w, s0[lj]))));
                s1[lj] = fmaf(q.x, c.x, fmaf(q.y, c.y, fmaf(q.z, c.z, fmaf(q.w, c.w, s1[lj]))));
            }
        }
    }
    #pragma unroll
    for (int lj = 0; lj < TJ; lj++) {
        s0[lj] += rpb_s[(p0 + 6 - di)*13 + (c0 + 6 - dj[lj])];
        s1[lj] += rpb_s[(p1 + 6 - di)*13 + (c1 + 6 - dj[lj])];
        if (lane >= 17) s1[lj] = -1e30f;
    }

    // ---- softmax: 4 parallel butterflies ----
    float mx[TJ], se[TJ], e0[TJ], e1[TJ];
    #pragma unroll
    for (int lj = 0; lj < TJ; lj++) mx[lj] = fmaxf(s0[lj], s1[lj]);
    #pragma unroll
    for (int o = 16; o > 0; o >>= 1)
        #pragma unroll
        for (int lj = 0; lj < TJ; lj++)
            mx[lj] = fmaxf(mx[lj], __shfl_xor_sync(0xffffffffu, mx[lj], o));
    #pragma unroll
    for (int lj = 0; lj < TJ; lj++) {
        e0[lj] = __expf(s0[lj] - mx[lj]);
        e1[lj] = (lane < 17) ? __expf(s1[lj] - mx[lj]) : 0.f;
        se[lj] = e0[lj] + e1[lj];
    }
    #pragma unroll
    for (int o = 16; o > 0; o >>= 1)
        #pragma unroll
        for (int lj = 0; lj < TJ; lj++)
            se[lj] += __shfl_xor_sync(0xffffffffu, se[lj], o);

    // ---- scatter weights (absolute staged columns, zero-padded grid) ----
    #pragma unroll
    for (int lj = 0; lj < TJ; lj++) {
        float inv = 1.f / se[lj];
        float* wrow = Ws + (wid*4 + lj)*SWS;
        wrow[p0*NCOL + cb[lj] + c0] = e0[lj] * inv;
        if (lane < 17)
            wrow[p1*NCOL + cb[lj] + c1] = e1[lj] * inv;
    }
    __syncwarp();

    // ---- AV: union sweep, V read once per warp ----
    {
        int pl = lane >> 3;          // pixel within warp row
        int dg = lane & 7;           // float4 channel group
        int pix = wid*4 + pl;
        const float* wrow = Ws + pix*SWS;
        float4 acc = make_float4(0.f, 0.f, 0.f, 0.f);

        #pragma unroll
        for (int p = 0; p < KS; p++) {
            const float* vbase = &Vs[((rb + p)*NCOL)*SKV + dg*4];
            const float* wbase = wrow + p*NCOL;
            #pragma unroll
            for (int c = 0; c < NCOL; c++) {
                float w = wbase[c];
                float4 v = *(const float4*)(vbase + c*SKV);
                acc.x = fmaf(w, v.x, acc.x);
                acc.y = fmaf(w, v.y, acc.y);
                acc.z = fmaf(w, v.z, acc.z);
                acc.w = fmaf(w, v.w, acc.w);
            }
        }
        int j = j0 + pl;
        int tok = (b*HH + i)*WW + j;
        *(float4*)&out[tok*CC + h*DH + dg*4] = acc;
    }
}

// ---------------------------------------------------------------------------
// LayerNorm + NHWC -> NCHW
// ---------------------------------------------------------------------------
__global__ __launch_bounds__(256) void ln_out_kernel(
    const float* __restrict__ y,
    const float* __restrict__ gamma,
    const float* __restrict__ beta,
    float* __restrict__ out)
{
    __shared__ float sh[32][129];
    int tok0 = blockIdx.x * 32;
    int b   = tok0 >> 12;
    int hw0 = tok0 & 4095;
    int w = threadIdx.x >> 5, lane = threadIdx.x & 31;

    #pragma unroll
    for (int t = w*4; t < w*4 + 4; t++) {
        int tok = tok0 + t;
        float v0 = y[tok*CC + lane];
        float v1 = y[tok*CC + lane + 32];
        float v2 = y[tok*CC + lane + 64];
        float v3 = y[tok*CC + lane + 96];
        float s  = v0 + v1 + v2 + v3;
        float s2 = v0*v0 + v1*v1 + v2*v2 + v3*v3;
        #pragma unroll
        for (int o = 16; o > 0; o >>= 1) {
            s  += __shfl_xor_sync(0xffffffffu, s,  o);
            s2 += __shfl_xor_sync(0xffffffffu, s2, o);
        }
        float mu  = s * (1.f/128.f);
        float var = s2 * (1.f/128.f) - mu*mu;
        float rs  = rsqrtf(var + 1e-5f);
        sh[t][lane]      = (v0 - mu)*rs*gamma[lane]      + beta[lane];
        sh[t][lane + 32] = (v1 - mu)*rs*gamma[lane + 32] + beta[lane + 32];
        sh[t][lane + 64] = (v2 - mu)*rs*gamma[lane + 64] + beta[lane + 64];
        sh[t][lane + 96] = (v3 - mu)*rs*gamma[lane + 96] + beta[lane + 96];
    }
    __syncthreads();

    for (int c = w; c < CC; c += 8)
        out[((b*CC + c)*(HH*WW)) + hw0 + lane] = sh[lane][c];
}

// ---------------------------------------------------------------------------
// Launch
// ---------------------------------------------------------------------------
extern "C" void kernel_launch(void* const* d_in, const int* in_sizes, int n_in,
                              void* d_out, int out_size)
{
    const float* x      = (const float*)d_in[0];
    const float* qkv_w  = (const float*)d_in[1];
    const float* qkv_b  = (const float*)d_in[2];
    const float* rpb    = (const float*)d_in[3];
    const float* proj_w = (const float*)d_in[4];
    const float* proj_b = (const float*)d_in[5];
    const float* ln_g   = (const float*)d_in[6];
    const float* ln_b   = (const float*)d_in[7];
    float* out = (float*)d_out;

    float *y, *qkv, *att, *wq, *wp;
    cudaGetSymbolAddress((void**)&y,   g_y);
    cudaGetSymbolAddress((void**)&qkv, g_qkv);
    cudaGetSymbolAddress((void**)&att, g_att);
    cudaGetSymbolAddress((void**)&wq,  g_wq);
    cudaGetSymbolAddress((void**)&wp,  g_wp);

    static int smem_set = 0;
    if (!smem_set) {
        cudaFuncSetAttribute(gemm_tc_kernel,
                             cudaFuncAttributeMaxDynamicSharedMemorySize, GEMM_SMEM);
        cudaFuncSetAttribute(attn_kernel,
                             cudaFuncAttributeMaxDynamicSharedMemorySize, ATTN_SMEM);
        smem_set = 1;
    }

    cvt_w_kernel<<<512, 256>>>(qkv_w, proj_w, wq, wp);

    {
        dim3 grid(HH*WW/32, CC/32, BB), block(32, 8);
        transpose_in_kernel<<<grid, block>>>(x, y);
    }

    for (int l = 0; l < 2; l++) {
        {
            dim3 grid(TOKENS/64, 384/64);
            gemm_tc_kernel<<<grid, 256, GEMM_SMEM>>>(y, wq + l*384*128, qkv_b + l*384,
                                                     qkv, 384, 1);
        }
        {
            dim3 grid(WW/TJ, HH/TI, BB*NH);
            attn_kernel<<<grid, 256, ATTN_SMEM>>>(qkv, rpb + l*NH*13*13, att);
        }
        {
            dim3 grid(TOKENS/64, 128/64);
            gemm_tc_kernel<<<grid, 256, GEMM_SMEM>>>(att, wp + l*128*128, proj_b + l*128,
                                                     y, 128, 0);
        }
    }

    ln_out_kernel<<<TOKENS/32, 256>>>(y, ln_g, ln_b, out);
}

// round 14
// speedup vs baseline: 1.0726x; 1.0726x over previous
#include <cuda_runtime.h>
#include <math.h>
#include <stdint.h>

// Problem constants
#define BB 2
#define CC 128
#define HH 64
#define WW 64
#define NH 4
#define DH 32
#define KS 7
#define TOKENS (BB*HH*WW)   // 8192

// Attention tile config
#define TI 8
#define TJ 4
#define NROW 14
#define NCOL 10
#define NPIX (NROW*NCOL)    // 140
#define KROWS 144           // K rows incl. 4 pad rows (sweep reads up to 141)
#define SKV 36              // Q/K/V smem stride
#define SWS 72              // score/weight smem stride

// Scratch (device globals: no allocation allowed)
__device__ float g_y[TOKENS*CC];
__device__ float g_qkv[TOKENS*3*CC];
__device__ float g_att[TOKENS*CC];
__device__ float g_wq[2*384*128];   // tf32-rounded qkv weights
__device__ float g_wp[2*128*128];   // tf32-rounded proj weights

__device__ __forceinline__ uint32_t f2tf32(float x)
{
    uint32_t r;
    asm("cvt.rna.tf32.f32 %0, %1;" : "=r"(r) : "f"(x));
    return r;
}

__device__ __forceinline__ void mma_tf32(float* d, const uint32_t* a, const uint32_t* b)
{
    asm volatile("mma.sync.aligned.m16n8k8.row.col.f32.tf32.tf32.f32 "
        "{%0,%1,%2,%3}, {%4,%5,%6,%7}, {%8,%9}, {%0,%1,%2,%3};"
        : "+f"(d[0]), "+f"(d[1]), "+f"(d[2]), "+f"(d[3])
        : "r"(a[0]), "r"(a[1]), "r"(a[2]), "r"(a[3]), "r"(b[0]), "r"(b[1]));
}

// ---------------------------------------------------------------------------
// One-shot weight conversion fp32 -> tf32 bit pattern
// ---------------------------------------------------------------------------
__global__ void cvt_w_kernel(const float* __restrict__ qkv_w,
                             const float* __restrict__ proj_w,
                             float* __restrict__ wq,
                             float* __restrict__ wp)
{
    int idx = blockIdx.x * blockDim.x + threadIdx.x;
    const int NQ = 2*384*128;
    const int NP = 2*128*128;
    if (idx < NQ)
        wq[idx] = __uint_as_float(f2tf32(qkv_w[idx]));
    else if (idx < NQ + NP)
        wp[idx - NQ] = __uint_as_float(f2tf32(proj_w[idx - NQ]));
}

// ---------------------------------------------------------------------------
// NCHW -> NHWC transpose
// ---------------------------------------------------------------------------
__global__ void transpose_in_kernel(const float* __restrict__ x, float* __restrict__ y)
{
    __shared__ float tile[32][33];
    int b   = blockIdx.z;
    int hw0 = blockIdx.x * 32;
    int c0  = blockIdx.y * 32;
    int tx = threadIdx.x, ty = threadIdx.y;
    #pragma unroll
    for (int k = 0; k < 32; k += 8)
        tile[ty + k][tx] = x[((b*CC + c0 + ty + k) * (HH*WW)) + hw0 + tx];
    __syncthreads();
    #pragma unroll
    for (int k = 0; k < 32; k += 8)
        y[(b*(HH*WW) + hw0 + ty + k)*CC + c0 + tx] = tile[tx][ty + k];
}

// ---------------------------------------------------------------------------
// tf32 tensor-core GEMM, single-stage full-K smem. (unchanged)
// ---------------------------------------------------------------------------
#define SK 132

__global__ __launch_bounds__(256) void gemm_tc_kernel(
    const float* __restrict__ A,
    const float* __restrict__ W,      // tf32 bits
    const float* __restrict__ bias,
    float* __restrict__ C,
    int N, int scale_q)
{
    extern __shared__ uint32_t smg[];
    uint32_t* As = smg;
    uint32_t* Bs = smg + 64*SK;

    int m0 = blockIdx.x * 64;
    int n0 = blockIdx.y * 64;
    int tid  = threadIdx.x;
    int lane = tid & 31;
    int wid  = tid >> 5;
    int wm = wid & 1;
    int wn = wid >> 1;
    int gp = lane >> 2;
    int tg = lane & 3;

    const float* Ag = A + (m0 + wid)*128 + lane*4;
    const float* Wg = W + (n0 + wid)*128 + lane*4;
    #pragma unroll
    for (int s = 0; s < 8; s++) {
        float4 a = *(const float4*)(Ag + s*8*128);
        float4 b = *(const float4*)(Wg + s*8*128);
        uint4 ua = make_uint4(f2tf32(a.x), f2tf32(a.y), f2tf32(a.z), f2tf32(a.w));
        uint4 ub = make_uint4(__float_as_uint(b.x), __float_as_uint(b.y),
                              __float_as_uint(b.z), __float_as_uint(b.w));
        *(uint4*)&As[(wid + s*8)*SK + lane*4] = ua;
        *(uint4*)&Bs[(wid + s*8)*SK + lane*4] = ub;
    }
    __syncthreads();

    float acc[2][2][4];
    #pragma unroll
    for (int mt = 0; mt < 2; mt++)
        #pragma unroll
        for (int nt = 0; nt < 2; nt++)
            #pragma unroll
            for (int c = 0; c < 4; c++) acc[mt][nt][c] = 0.f;

    #pragma unroll
    for (int ks = 0; ks < 16; ks++) {
        int kb = ks*8;
        uint32_t af[2][4], bf[2][2];
        #pragma unroll
        for (int mt = 0; mt < 2; mt++) {
            int r = wm*32 + mt*16 + gp;
            af[mt][0] = As[r*SK     + kb + tg    ];
            af[mt][1] = As[(r+8)*SK + kb + tg    ];
            af[mt][2] = As[r*SK     + kb + tg + 4];
            af[mt][3] = As[(r+8)*SK + kb + tg + 4];
        }
        #pragma unroll
        for (int nt = 0; nt < 2; nt++) {
            int c = wn*16 + nt*8 + gp;
            bf[nt][0] = Bs[c*SK + kb + tg    ];
            bf[nt][1] = Bs[c*SK + kb + tg + 4];
        }
        #pragma unroll
        for (int mt = 0; mt < 2; mt++)
            #pragma unroll
            for (int nt = 0; nt < 2; nt++)
                mma_tf32(acc[mt][nt], af[mt], bf[nt]);
    }

    const float qs = 0.17677669529663687f;
    #pragma unroll
    for (int mt = 0; mt < 2; mt++) {
        int rbase = m0 + wm*32 + mt*16 + gp;
        #pragma unroll
        for (int nt = 0; nt < 2; nt++) {
            int col = n0 + wn*16 + nt*8 + 2*tg;
            float b0 = bias[col], b1 = bias[col + 1];
            float sc = (scale_q && col < 128) ? qs : 1.f;
            float2 v0 = make_float2((acc[mt][nt][0] + b0)*sc, (acc[mt][nt][1] + b1)*sc);
            float2 v1 = make_float2((acc[mt][nt][2] + b0)*sc, (acc[mt][nt][3] + b1)*sc);
            *(float2*)&C[rbase*N + col]       = v0;
            *(float2*)&C[(rbase + 8)*N + col] = v1;
        }
    }
}
#define GEMM_SMEM (2*64*SK*4)

// ---------------------------------------------------------------------------
// Neighborhood attention v5: union-sweep QK with broadcast K reads.
// Block = (head, 8x4 tile), 256 threads, warp w -> pixel row i0+w.
// QK: lane=(pixel,chunk); warp sweeps the 70-cell union; per cell one
//     broadcast LDS.128 (128B) + dot4 partial; 8-cell batches reduced by a
//     3-stage select/shuffle butterfly (7 SHFL / 8 cells); scores -> smem.
// Softmax: lane=neighbor reads scores, butterfly-normalizes, zeroes the row,
//          scatters weights zero-padded in absolute sweep coords.
// AV: union sweep, V broadcast reads (unchanged).
// ---------------------------------------------------------------------------
#define ATTN_SMEM ((32*SKV + KROWS*SKV + NPIX*SKV + 32*SWS + 176)*4)

__global__ __launch_bounds__(256) void attn_kernel(
    const float* __restrict__ qkv,
    const float* __restrict__ rpb,
    float* __restrict__ out)
{
    extern __shared__ float sma[];
    float* Qs = sma;                    // [32][SKV]
    float* Ks = Qs + 32*SKV;            // [KROWS][SKV]
    float* Vs = Ks + KROWS*SKV;         // [NPIX][SKV]
    float* Sw = Vs + NPIX*SKV;          // [32][SWS]  scores -> weights in place
    float* rpb_s = Sw + 32*SWS;         // [169]

    int j0 = blockIdx.x * TJ;
    int i0 = blockIdx.y * TI;
    int bh = blockIdx.z;
    int b  = bh >> 2;
    int h  = bh & 3;

    int tid  = threadIdx.x;
    int wid  = tid >> 5;
    int lane = tid & 31;

    int rbase = i0 - 3; rbase = rbase < 0 ? 0 : (rbase > HH-NROW ? HH-NROW : rbase);
    int cbase = j0 - 3; cbase = cbase < 0 ? 0 : (cbase > WW-NCOL ? WW-NCOL : cbase);

    // ---- stage Q, K, V, rpb; zero K pad rows ----
    for (int pix = wid; pix < 32; pix += 8) {
        int i = i0 + (pix >> 2), j = j0 + (pix & 3);
        Qs[pix*SKV + lane] = qkv[((b*HH + i)*WW + j)*384 + h*DH + lane];
    }
    {
        int gi = 0, gj = wid;   // wid < 8 < NCOL
        for (int r = wid; r < NPIX; r += 8) {
            const float* base = qkv + (((b*HH + rbase + gi)*WW) + cbase + gj)*384 + h*DH;
            Ks[r*SKV + lane] = base[128 + lane];
            Vs[r*SKV + lane] = base[256 + lane];
            gj += 8; if (gj >= NCOL) { gj -= NCOL; gi++; }
        }
    }
    if (tid < (KROWS-NPIX)*SKV) Ks[NPIX*SKV + tid] = 0.f;
    if (tid < 169) rpb_s[tid] = rpb[h*169 + tid];
    __syncthreads();

    int i  = i0 + wid;
    int si = i - 3; si = si < 0 ? 0 : (si > HH-KS ? HH-KS : si);
    int rb = si - rbase;
    int di = i - si;
    int rb10 = rb*NCOL;

    // ---- QK union sweep: lane = (pl, dg) ----
    {
        int pl = lane >> 3;
        int dg = lane & 7;
        int pix = wid*4 + pl;
        float4 q = *(const float4*)&Qs[pix*SKV + dg*4];
        bool b2 = (dg & 4) != 0, b1 = (dg & 2) != 0, b0 = (dg & 1) != 0;

        #pragma unroll
        for (int r = 0; r < 9; r++) {
            int base = r*8;
            float p[8];
            #pragma unroll
            for (int jj = 0; jj < 8; jj++) {
                const float4 k = *(const float4*)&Ks[(rb10 + base + jj)*SKV + dg*4];
                p[jj] = fmaf(q.x, k.x, fmaf(q.y, k.y, fmaf(q.z, k.z, q.w*k.w)));
            }
            // stage 1 (xor 4): keep cells with bit2 == bit2(dg)
            float s1[4];
            #pragma unroll
            for (int jj = 0; jj < 4; jj++) {
                float snd = b2 ? p[jj] : p[jj+4];
                float rcv = __shfl_xor_sync(0xffffffffu, snd, 4);
                s1[jj] = (b2 ? p[jj+4] : p[jj]) + rcv;
            }
            // stage 2 (xor 2)
            float s2[2];
            #pragma unroll
            for (int jj = 0; jj < 2; jj++) {
                float snd = b1 ? s1[jj] : s1[jj+2];
                float rcv = __shfl_xor_sync(0xffffffffu, snd, 2);
                s2[jj] = (b1 ? s1[jj+2] : s1[jj]) + rcv;
            }
            // stage 3 (xor 1): lane dg ends with cell base+dg
            float snd = b0 ? s2[0] : s2[1];
            float rcv = __shfl_xor_sync(0xffffffffu, snd, 1);
            float s3  = (b0 ? s2[1] : s2[0]) + rcv;

            Sw[pix*SWS + base + dg] = s3;
        }
    }
    __syncwarp();

    // ---- softmax per pixel: lane = neighbor ----
    int p0 = lane / KS, c0 = lane % KS;
    int n1 = lane + 32; if (n1 > 48) n1 = 48;
    int p1 = n1 / KS, c1 = n1 % KS;

    int cb[TJ], dj[TJ];
    #pragma unroll
    for (int lj = 0; lj < TJ; lj++) {
        int j  = j0 + lj;
        int sj = j - 3; sj = sj < 0 ? 0 : (sj > WW-KS ? WW-KS : sj);
        cb[lj] = sj - cbase;
        dj[lj] = j - sj;
    }

    float s0[TJ], s1v[TJ];
    #pragma unroll
    for (int lj = 0; lj < TJ; lj++) {
        const float* srow = Sw + (wid*4 + lj)*SWS;
        s0[lj]  = srow[p0*NCOL + cb[lj] + c0] + rpb_s[(p0 + 6 - di)*13 + (c0 + 6 - dj[lj])];
        s1v[lj] = srow[p1*NCOL + cb[lj] + c1] + rpb_s[(p1 + 6 - di)*13 + (c1 + 6 - dj[lj])];
        if (lane >= 17) s1v[lj] = -1e30f;
    }

    float mx[TJ], se[TJ], e0[TJ], e1[TJ];
    #pragma unroll
    for (int lj = 0; lj < TJ; lj++) mx[lj] = fmaxf(s0[lj], s1v[lj]);
    #pragma unroll
    for (int o = 16; o > 0; o >>= 1)
        #pragma unroll
        for (int lj = 0; lj < TJ; lj++)
            mx[lj] = fmaxf(mx[lj], __shfl_xor_sync(0xffffffffu, mx[lj], o));
    #pragma unroll
    for (int lj = 0; lj < TJ; lj++) {
        e0[lj] = __expf(s0[lj] - mx[lj]);
        e1[lj] = (lane < 17) ? __expf(s1v[lj] - mx[lj]) : 0.f;
        se[lj] = e0[lj] + e1[lj];
    }
    #pragma unroll
    for (int o = 16; o > 0; o >>= 1)
        #pragma unroll
        for (int lj = 0; lj < TJ; lj++)
            se[lj] += __shfl_xor_sync(0xffffffffu, se[lj], o);

    __syncwarp();
    // zero weight rows (scores consumed), then scatter
    #pragma unroll
    for (int lj = 0; lj < TJ; lj++) {
        float* wrow = Sw + (wid*4 + lj)*SWS;
        wrow[lane] = 0.f;
        wrow[32 + lane] = 0.f;
        if (lane < 8) wrow[64 + lane] = 0.f;
    }
    __syncwarp();
    #pragma unroll
    for (int lj = 0; lj < TJ; lj++) {
        float inv = 1.f / se[lj];
        float* wrow = Sw + (wid*4 + lj)*SWS;
        wrow[p0*NCOL + cb[lj] + c0] = e0[lj] * inv;
        if (lane < 17)
            wrow[p1*NCOL + cb[lj] + c1] = e1[lj] * inv;
    }
    __syncwarp();

    // ---- AV: union sweep, broadcast V reads ----
    {
        int pl = lane >> 3;
        int dg = lane & 7;
        int pix = wid*4 + pl;
        const float* wrow = Sw + pix*SWS;
        float4 acc = make_float4(0.f, 0.f, 0.f, 0.f);

        #pragma unroll
        for (int p = 0; p < KS; p++) {
            const float* vbase = &Vs[((rb + p)*NCOL)*SKV + dg*4];
            const float* wbase = wrow + p*NCOL;
            #pragma unroll
            for (int c = 0; c < NCOL; c++) {
                float w = wbase[c];
                float4 v = *(const float4*)(vbase + c*SKV);
                acc.x = fmaf(w, v.x, acc.x);
                acc.y = fmaf(w, v.y, acc.y);
                acc.z = fmaf(w, v.z, acc.z);
                acc.w = fmaf(w, v.w, acc.w);
            }
        }
        int j = j0 + pl;
        int tok = (b*HH + i)*WW + j;
        *(float4*)&out[tok*CC + h*DH + dg*4] = acc;
    }
}

// ---------------------------------------------------------------------------
// LayerNorm + NHWC -> NCHW
// ---------------------------------------------------------------------------
__global__ __launch_bounds__(256) void ln_out_kernel(
    const float* __restrict__ y,
    const float* __restrict__ gamma,
    const float* __restrict__ beta,
    float* __restrict__ out)
{
    __shared__ float sh[32][129];
    int tok0 = blockIdx.x * 32;
    int b   = tok0 >> 12;
    int hw0 = tok0 & 4095;
    int w = threadIdx.x >> 5, lane = threadIdx.x & 31;

    #pragma unroll
    for (int t = w*4; t < w*4 + 4; t++) {
        int tok = tok0 + t;
        float v0 = y[tok*CC + lane];
        float v1 = y[tok*CC + lane + 32];
        float v2 = y[tok*CC + lane + 64];
        float v3 = y[tok*CC + lane + 96];
        float s  = v0 + v1 + v2 + v3;
        float s2 = v0*v0 + v1*v1 + v2*v2 + v3*v3;
        #pragma unroll
        for (int o = 16; o > 0; o >>= 1) {
            s  += __shfl_xor_sync(0xffffffffu, s,  o);
            s2 += __shfl_xor_sync(0xffffffffu, s2, o);
        }
        float mu  = s * (1.f/128.f);
        float var = s2 * (1.f/128.f) - mu*mu;
        float rs  = rsqrtf(var + 1e-5f);
        sh[t][lane]      = (v0 - mu)*rs*gamma[lane]      + beta[lane];
        sh[t][lane + 32] = (v1 - mu)*rs*gamma[lane + 32] + beta[lane + 32];
        sh[t][lane + 64] = (v2 - mu)*rs*gamma[lane + 64] + beta[lane + 64];
        sh[t][lane + 96] = (v3 - mu)*rs*gamma[lane + 96] + beta[lane + 96];
    }
    __syncthreads();

    for (int c = w; c < CC; c += 8)
        out[((b*CC + c)*(HH*WW)) + hw0 + lane] = sh[lane][c];
}

// ---------------------------------------------------------------------------
// Launch
// ---------------------------------------------------------------------------
extern "C" void kernel_launch(void* const* d_in, const int* in_sizes, int n_in,
                              void* d_out, int out_size)
{
    const float* x      = (const float*)d_in[0];
    const float* qkv_w  = (const float*)d_in[1];
    const float* qkv_b  = (const float*)d_in[2];
    const float* rpb    = (const float*)d_in[3];
    const float* proj_w = (const float*)d_in[4];
    const float* proj_b = (const float*)d_in[5];
    const float* ln_g   = (const float*)d_in[6];
    const float* ln_b   = (const float*)d_in[7];
    float* out = (float*)d_out;

    float *y, *qkv, *att, *wq, *wp;
    cudaGetSymbolAddress((void**)&y,   g_y);
    cudaGetSymbolAddress((void**)&qkv, g_qkv);
    cudaGetSymbolAddress((void**)&att, g_att);
    cudaGetSymbolAddress((void**)&wq,  g_wq);
    cudaGetSymbolAddress((void**)&wp,  g_wp);

    static int smem_set = 0;
    if (!smem_set) {
        cudaFuncSetAttribute(gemm_tc_kernel,
                             cudaFuncAttributeMaxDynamicSharedMemorySize, GEMM_SMEM);
        cudaFuncSetAttribute(attn_kernel,
                             cudaFuncAttributeMaxDynamicSharedMemorySize, ATTN_SMEM);
        smem_set = 1;
    }

    cvt_w_kernel<<<512, 256>>>(qkv_w, proj_w, wq, wp);

    {
        dim3 grid(HH*WW/32, CC/32, BB), block(32, 8);
        transpose_in_kernel<<<grid, block>>>(x, y);
    }

    for (int l = 0; l < 2; l++) {
        {
            dim3 grid(TOKENS/64, 384/64);
            gemm_tc_kernel<<<grid, 256, GEMM_SMEM>>>(y, wq + l*384*128, qkv_b + l*384,
                                                     qkv, 384, 1);
        }
        {
            dim3 grid(WW/TJ, HH/TI, BB*NH);
            attn_kernel<<<grid, 256, ATTN_SMEM>>>(qkv, rpb + l*NH*13*13, att);
        }
        {
            dim3 grid(TOKENS/64, 128/64);
            gemm_tc_kernel<<<grid, 256, GEMM_SMEM>>>(att, wp + l*128*128, proj_b + l*128,
                                                     y, 128, 0);
        }
    }

    ln_out_kernel<<<TOKENS/32, 256>>>(y, ln_g, ln_b, out);
}

// round 16
// speedup vs baseline: 1.1945x; 1.1137x over previous
#include <cuda_runtime.h>
#include <cuda_fp16.h>
#include <math.h>
#include <stdint.h>

// Problem constants
#define BB 2
#define CC 128
#define HH 64
#define WW 64
#define NH 4
#define DH 32
#define KS 7
#define TOKENS (BB*HH*WW)   // 8192

// Attention tile config
#define TI 8
#define TJ 4
#define NROW 14
#define NCOL 10
#define NPIX (NROW*NCOL)    // 140
#define KROWS 144           // K rows incl. pad (sweep reads up to 141)
#define SKV 36              // Q smem stride (floats)
#define SKH 36              // K/V smem stride (halves)
#define SWW 88              // score/weight smem stride (floats)

// Scratch (device globals: no allocation allowed)
__device__ float g_y[TOKENS*CC];
__device__ float g_qkv[TOKENS*3*CC];
__device__ float g_att[TOKENS*CC];
__device__ float g_wq[2*384*128];   // tf32-rounded qkv weights
__device__ float g_wp[2*128*128];   // tf32-rounded proj weights

__device__ __forceinline__ uint32_t f2tf32(float x)
{
    uint32_t r;
    asm("cvt.rna.tf32.f32 %0, %1;" : "=r"(r) : "f"(x));
    return r;
}

__device__ __forceinline__ void mma_tf32(float* d, const uint32_t* a, const uint32_t* b)
{
    asm volatile("mma.sync.aligned.m16n8k8.row.col.f32.tf32.tf32.f32 "
        "{%0,%1,%2,%3}, {%4,%5,%6,%7}, {%8,%9}, {%0,%1,%2,%3};"
        : "+f"(d[0]), "+f"(d[1]), "+f"(d[2]), "+f"(d[3])
        : "r"(a[0]), "r"(a[1]), "r"(a[2]), "r"(a[3]), "r"(b[0]), "r"(b[1]));
}

// load 4 halves (8B) from smem and convert to 4 floats
__device__ __forceinline__ float4 ldsm_h4(const __half* p)
{
    uint2 raw = *(const uint2*)p;
    __half2 a = *(__half2*)&raw.x;
    __half2 b = *(__half2*)&raw.y;
    float2 fa = __half22float2(a);
    float2 fb = __half22float2(b);
    return make_float4(fa.x, fa.y, fb.x, fb.y);
}

// ---------------------------------------------------------------------------
// One-shot weight conversion fp32 -> tf32 bit pattern
// ---------------------------------------------------------------------------
__global__ void cvt_w_kernel(const float* __restrict__ qkv_w,
                             const float* __restrict__ proj_w,
                             float* __restrict__ wq,
                             float* __restrict__ wp)
{
    int idx = blockIdx.x * blockDim.x + threadIdx.x;
    const int NQ = 2*384*128;
    const int NP = 2*128*128;
    if (idx < NQ)
        wq[idx] = __uint_as_float(f2tf32(qkv_w[idx]));
    else if (idx < NQ + NP)
        wp[idx - NQ] = __uint_as_float(f2tf32(proj_w[idx - NQ]));
}

// ---------------------------------------------------------------------------
// NCHW -> NHWC transpose
// ---------------------------------------------------------------------------
__global__ void transpose_in_kernel(const float* __restrict__ x, float* __restrict__ y)
{
    __shared__ float tile[32][33];
    int b   = blockIdx.z;
    int hw0 = blockIdx.x * 32;
    int c0  = blockIdx.y * 32;
    int tx = threadIdx.x, ty = threadIdx.y;
    #pragma unroll
    for (int k = 0; k < 32; k += 8)
        tile[ty + k][tx] = x[((b*CC + c0 + ty + k) * (HH*WW)) + hw0 + tx];
    __syncthreads();
    #pragma unroll
    for (int k = 0; k < 32; k += 8)
        y[(b*(HH*WW) + hw0 + ty + k)*CC + c0 + tx] = tile[tx][ty + k];
}

// ---------------------------------------------------------------------------
// tf32 tensor-core GEMM, single-stage full-K smem. (unchanged)
// ---------------------------------------------------------------------------
#define SK 132

__global__ __launch_bounds__(256) void gemm_tc_kernel(
    const float* __restrict__ A,
    const float* __restrict__ W,      // tf32 bits
    const float* __restrict__ bias,
    float* __restrict__ C,
    int N, int scale_q)
{
    extern __shared__ uint32_t smg[];
    uint32_t* As = smg;
    uint32_t* Bs = smg + 64*SK;

    int m0 = blockIdx.x * 64;
    int n0 = blockIdx.y * 64;
    int tid  = threadIdx.x;
    int lane = tid & 31;
    int wid  = tid >> 5;
    int wm = wid & 1;
    int wn = wid >> 1;
    int gp = lane >> 2;
    int tg = lane & 3;

    const float* Ag = A + (m0 + wid)*128 + lane*4;
    const float* Wg = W + (n0 + wid)*128 + lane*4;
    #pragma unroll
    for (int s = 0; s < 8; s++) {
        float4 a = *(const float4*)(Ag + s*8*128);
        float4 b = *(const float4*)(Wg + s*8*128);
        uint4 ua = make_uint4(f2tf32(a.x), f2tf32(a.y), f2tf32(a.z), f2tf32(a.w));
        uint4 ub = make_uint4(__float_as_uint(b.x), __float_as_uint(b.y),
                              __float_as_uint(b.z), __float_as_uint(b.w));
        *(uint4*)&As[(wid + s*8)*SK + lane*4] = ua;
        *(uint4*)&Bs[(wid + s*8)*SK + lane*4] = ub;
    }
    __syncthreads();

    float acc[2][2][4];
    #pragma unroll
    for (int mt = 0; mt < 2; mt++)
        #pragma unroll
        for (int nt = 0; nt < 2; nt++)
            #pragma unroll
            for (int c = 0; c < 4; c++) acc[mt][nt][c] = 0.f;

    #pragma unroll
    for (int ks = 0; ks < 16; ks++) {
        int kb = ks*8;
        uint32_t af[2][4], bf[2][2];
        #pragma unroll
        for (int mt = 0; mt < 2; mt++) {
            int r = wm*32 + mt*16 + gp;
            af[mt][0] = As[r*SK     + kb + tg    ];
            af[mt][1] = As[(r+8)*SK + kb + tg    ];
            af[mt][2] = As[r*SK     + kb + tg + 4];
            af[mt][3] = As[(r+8)*SK + kb + tg + 4];
        }
        #pragma unroll
        for (int nt = 0; nt < 2; nt++) {
            int c = wn*16 + nt*8 + gp;
            bf[nt][0] = Bs[c*SK + kb + tg    ];
            bf[nt][1] = Bs[c*SK + kb + tg + 4];
        }
        #pragma unroll
        for (int mt = 0; mt < 2; mt++)
            #pragma unroll
            for (int nt = 0; nt < 2; nt++)
                mma_tf32(acc[mt][nt], af[mt], bf[nt]);
    }

    const float qs = 0.17677669529663687f;
    #pragma unroll
    for (int mt = 0; mt < 2; mt++) {
        int rbase = m0 + wm*32 + mt*16 + gp;
        #pragma unroll
        for (int nt = 0; nt < 2; nt++) {
            int col = n0 + wn*16 + nt*8 + 2*tg;
            float b0 = bias[col], b1 = bias[col + 1];
            float sc = (scale_q && col < 128) ? qs : 1.f;
            float2 v0 = make_float2((acc[mt][nt][0] + b0)*sc, (acc[mt][nt][1] + b1)*sc);
            float2 v1 = make_float2((acc[mt][nt][2] + b0)*sc, (acc[mt][nt][3] + b1)*sc);
            *(float2*)&C[rbase*N + col]       = v0;
            *(float2*)&C[(rbase + 8)*N + col] = v1;
        }
    }
}
#define GEMM_SMEM (2*64*SK*4)

// ---------------------------------------------------------------------------
// Neighborhood attention v6: fp16 K/V smem (6 blocks/SM), union-sweep QK,
// float4 weight loads in AV (stride-12 weight rows).
// ---------------------------------------------------------------------------
#define ATTN_SMEM (32*SKV*4 + KROWS*SKH*2 + NPIX*SKH*2 + 32*SWW*4 + 176*4)

__global__ __launch_bounds__(256, 6) void attn_kernel(
    const float* __restrict__ qkv,
    const float* __restrict__ rpb,
    float* __restrict__ out)
{
    extern __shared__ float sma[];
    float*  Qs   = sma;                                   // [32][SKV] fp32
    __half* Ksh  = (__half*)(Qs + 32*SKV);                // [KROWS][SKH]
    __half* Vsh  = Ksh + KROWS*SKH;                       // [NPIX][SKH]
    float*  Ww   = (float*)(Vsh + NPIX*SKH);              // [32][SWW] scores->weights
    float*  rpb_s = Ww + 32*SWW;                          // [169]

    int j0 = blockIdx.x * TJ;
    int i0 = blockIdx.y * TI;
    int bh = blockIdx.z;
    int b  = bh >> 2;
    int h  = bh & 3;

    int tid  = threadIdx.x;
    int wid  = tid >> 5;
    int lane = tid & 31;

    int rbase = i0 - 3; rbase = rbase < 0 ? 0 : (rbase > HH-NROW ? HH-NROW : rbase);
    int cbase = j0 - 3; cbase = cbase < 0 ? 0 : (cbase > WW-NCOL ? WW-NCOL : cbase);

    // ---- stage Q (fp32), K/V (fp16), rpb; zero K pad rows ----
    for (int pix = wid; pix < 32; pix += 8) {
        int i = i0 + (pix >> 2), j = j0 + (pix & 3);
        Qs[pix*SKV + lane] = qkv[((b*HH + i)*WW + j)*384 + h*DH + lane];
    }
    {
        int gi = 0, gj = wid;   // wid < 8 < NCOL
        for (int r = wid; r < NPIX; r += 8) {
            const float* base = qkv + (((b*HH + rbase + gi)*WW) + cbase + gj)*384 + h*DH;
            Ksh[r*SKH + lane] = __float2half_rn(base[128 + lane]);
            Vsh[r*SKH + lane] = __float2half_rn(base[256 + lane]);
            gj += 8; if (gj >= NCOL) { gj -= NCOL; gi++; }
        }
    }
    if (tid < (KROWS-NPIX)*SKH)
        Ksh[NPIX*SKH + tid] = __float2half_rn(0.f);
    if (tid < 169) rpb_s[tid] = rpb[h*169 + tid];
    __syncthreads();

    int i  = i0 + wid;
    int si = i - 3; si = si < 0 ? 0 : (si > HH-KS ? HH-KS : si);
    int rb = si - rbase;
    int di = i - si;
    int rb10 = rb*NCOL;

    // ---- QK union sweep: lane = (pl, dg); scores linear in Ww ----
    {
        int pl = lane >> 3;
        int dg = lane & 7;
        int pix = wid*4 + pl;
        float4 q = *(const float4*)&Qs[pix*SKV + dg*4];
        bool bb2 = (dg & 4) != 0, bb1 = (dg & 2) != 0, bb0 = (dg & 1) != 0;

        #pragma unroll
        for (int r = 0; r < 9; r++) {
            int base = r*8;
            float p[8];
            #pragma unroll
            for (int jj = 0; jj < 8; jj++) {
                float4 k = ldsm_h4(&Ksh[(rb10 + base + jj)*SKH + dg*4]);
                p[jj] = fmaf(q.x, k.x, fmaf(q.y, k.y, fmaf(q.z, k.z, q.w*k.w)));
            }
            float s1[4];
            #pragma unroll
            for (int jj = 0; jj < 4; jj++) {
                float snd = bb2 ? p[jj] : p[jj+4];
                float rcv = __shfl_xor_sync(0xffffffffu, snd, 4);
                s1[jj] = (bb2 ? p[jj+4] : p[jj]) + rcv;
            }
            float s2[2];
            #pragma unroll
            for (int jj = 0; jj < 2; jj++) {
                float snd = bb1 ? s1[jj] : s1[jj+2];
                float rcv = __shfl_xor_sync(0xffffffffu, snd, 2);
                s2[jj] = (bb1 ? s1[jj+2] : s1[jj]) + rcv;
            }
            float snd = bb0 ? s2[0] : s2[1];
            float rcv = __shfl_xor_sync(0xffffffffu, snd, 1);
            float s3  = (bb0 ? s2[1] : s2[0]) + rcv;

            Ww[pix*SWW + base + dg] = s3;
        }
    }
    __syncwarp();

    // ---- softmax per pixel: lane = neighbor (scores read linear) ----
    int p0 = lane / KS, c0 = lane % KS;
    int n1 = lane + 32; if (n1 > 48) n1 = 48;
    int p1 = n1 / KS, c1 = n1 % KS;

    int cb[TJ], dj[TJ];
    #pragma unroll
    for (int lj = 0; lj < TJ; lj++) {
        int j  = j0 + lj;
        int sj = j - 3; sj = sj < 0 ? 0 : (sj > WW-KS ? WW-KS : sj);
        cb[lj] = sj - cbase;
        dj[lj] = j - sj;
    }

    float s0[TJ], s1v[TJ];
    #pragma unroll
    for (int lj = 0; lj < TJ; lj++) {
        const float* srow = Ww + (wid*4 + lj)*SWW;
        s0[lj]  = srow[p0*NCOL + cb[lj] + c0] + rpb_s[(p0 + 6 - di)*13 + (c0 + 6 - dj[lj])];
        s1v[lj] = srow[p1*NCOL + cb[lj] + c1] + rpb_s[(p1 + 6 - di)*13 + (c1 + 6 - dj[lj])];
        if (lane >= 17) s1v[lj] = -1e30f;
    }

    float mx[TJ], se[TJ], e0[TJ], e1[TJ];
    #pragma unroll
    for (int lj = 0; lj < TJ; lj++) mx[lj] = fmaxf(s0[lj], s1v[lj]);
    #pragma unroll
    for (int o = 16; o > 0; o >>= 1)
        #pragma unroll
        for (int lj = 0; lj < TJ; lj++)
            mx[lj] = fmaxf(mx[lj], __shfl_xor_sync(0xffffffffu, mx[lj], o));
    #pragma unroll
    for (int lj = 0; lj < TJ; lj++) {
        e0[lj] = __expf(s0[lj] - mx[lj]);
        e1[lj] = (lane < 17) ? __expf(s1v[lj] - mx[lj]) : 0.f;
        se[lj] = e0[lj] + e1[lj];
    }
    #pragma unroll
    for (int o = 16; o > 0; o >>= 1)
        #pragma unroll
        for (int lj = 0; lj < TJ; lj++)
            se[lj] += __shfl_xor_sync(0xffffffffu, se[lj], o);

    __syncwarp();
    // zero weight area (stride-12 rows: 84 floats), then scatter
    #pragma unroll
    for (int lj = 0; lj < TJ; lj++) {
        float* wrow = Ww + (wid*4 + lj)*SWW;
        wrow[lane] = 0.f;
        wrow[32 + lane] = 0.f;
        if (lane < 20) wrow[64 + lane] = 0.f;
    }
    __syncwarp();
    #pragma unroll
    for (int lj = 0; lj < TJ; lj++) {
        float inv = 1.f / se[lj];
        float* wrow = Ww + (wid*4 + lj)*SWW;
        wrow[p0*12 + cb[lj] + c0] = e0[lj] * inv;
        if (lane < 17)
            wrow[p1*12 + cb[lj] + c1] = e1[lj] * inv;
    }
    __syncwarp();

    // ---- AV: union sweep, fp16 V, float4 weight loads ----
    {
        int pl = lane >> 3;
        int dg = lane & 7;
        int pix = wid*4 + pl;
        const float* wrow = Ww + pix*SWW;
        float4 acc = make_float4(0.f, 0.f, 0.f, 0.f);

        #pragma unroll
        for (int p = 0; p < KS; p++) {
            float4 w0 = *(const float4*)(wrow + p*12);
            float4 w1 = *(const float4*)(wrow + p*12 + 4);
            float2 w2 = *(const float2*)(wrow + p*12 + 8);
            float wreg[10] = {w0.x, w0.y, w0.z, w0.w,
                              w1.x, w1.y, w1.z, w1.w, w2.x, w2.y};
            const __half* vbase = &Vsh[((rb + p)*NCOL)*SKH + dg*4];
            #pragma unroll
            for (int c = 0; c < NCOL; c++) {
                float4 v = ldsm_h4(vbase + c*SKH);
                float w = wreg[c];
                acc.x = fmaf(w, v.x, acc.x);
                acc.y = fmaf(w, v.y, acc.y);
                acc.z = fmaf(w, v.z, acc.z);
                acc.w = fmaf(w, v.w, acc.w);
            }
        }
        int j = j0 + pl;
        int tok = (b*HH + i)*WW + j;
        *(float4*)&out[tok*CC + h*DH + dg*4] = acc;
    }
}

// ---------------------------------------------------------------------------
// LayerNorm + NHWC -> NCHW
// ---------------------------------------------------------------------------
__global__ __launch_bounds__(256) void ln_out_kernel(
    const float* __restrict__ y,
    const float* __restrict__ gamma,
    const float* __restrict__ beta,
    float* __restrict__ out)
{
    __shared__ float sh[32][129];
    int tok0 = blockIdx.x * 32;
    int b   = tok0 >> 12;
    int hw0 = tok0 & 4095;
    int w = threadIdx.x >> 5, lane = threadIdx.x & 31;

    #pragma unroll
    for (int t = w*4; t < w*4 + 4; t++) {
        int tok = tok0 + t;
        float v0 = y[tok*CC + lane];
        float v1 = y[tok*CC + lane + 32];
        float v2 = y[tok*CC + lane + 64];
        float v3 = y[tok*CC + lane + 96];
        float s  = v0 + v1 + v2 + v3;
        float s2 = v0*v0 + v1*v1 + v2*v2 + v3*v3;
        #pragma unroll
        for (int o = 16; o > 0; o >>= 1) {
            s  += __shfl_xor_sync(0xffffffffu, s,  o);
            s2 += __shfl_xor_sync(0xffffffffu, s2, o);
        }
        float mu  = s * (1.f/128.f);
        float var = s2 * (1.f/128.f) - mu*mu;
        float rs  = rsqrtf(var + 1e-5f);
        sh[t][lane]      = (v0 - mu)*rs*gamma[lane]      + beta[lane];
        sh[t][lane + 32] = (v1 - mu)*rs*gamma[lane + 32] + beta[lane + 32];
        sh[t][lane + 64] = (v2 - mu)*rs*gamma[lane + 64] + beta[lane + 64];
        sh[t][lane + 96] = (v3 - mu)*rs*gamma[lane + 96] + beta[lane + 96];
    }
    __syncthreads();

    for (int c = w; c < CC; c += 8)
        out[((b*CC + c)*(HH*WW)) + hw0 + lane] = sh[lane][c];
}

// ---------------------------------------------------------------------------
// Launch
// ---------------------------------------------------------------------------
extern "C" void kernel_launch(void* const* d_in, const int* in_sizes, int n_in,
                              void* d_out, int out_size)
{
    const float* x      = (const float*)d_in[0];
    const float* qkv_w  = (const float*)d_in[1];
    const float* qkv_b  = (const float*)d_in[2];
    const float* rpb    = (const float*)d_in[3];
    const float* proj_w = (const float*)d_in[4];
    const float* proj_b = (const float*)d_in[5];
    const float* ln_g   = (const float*)d_in[6];
    const float* ln_b   = (const float*)d_in[7];
    float* out = (float*)d_out;

    float *y, *qkv, *att, *wq, *wp;
    cudaGetSymbolAddress((void**)&y,   g_y);
    cudaGetSymbolAddress((void**)&qkv, g_qkv);
    cudaGetSymbolAddress((void**)&att, g_att);
    cudaGetSymbolAddress((void**)&wq,  g_wq);
    cudaGetSymbolAddress((void**)&wp,  g_wp);

    static int smem_set = 0;
    if (!smem_set) {
        cudaFuncSetAttribute(gemm_tc_kernel,
                             cudaFuncAttributeMaxDynamicSharedMemorySize, GEMM_SMEM);
        cudaFuncSetAttribute(attn_kernel,
                             cudaFuncAttributeMaxDynamicSharedMemorySize, ATTN_SMEM);
        smem_set = 1;
    }

    cvt_w_kernel<<<512, 256>>>(qkv_w, proj_w, wq, wp);

    {
        dim3 grid(HH*WW/32, CC/32, BB), block(32, 8);
        transpose_in_kernel<<<grid, block>>>(x, y);
    }

    for (int l = 0; l < 2; l++) {
        {
            dim3 grid(TOKENS/64, 384/64);
            gemm_tc_kernel<<<grid, 256, GEMM_SMEM>>>(y, wq + l*384*128, qkv_b + l*384,
                                                     qkv, 384, 1);
        }
        {
            dim3 grid(WW/TJ, HH/TI, BB*NH);
            attn_kernel<<<grid, 256, ATTN_SMEM>>>(qkv, rpb + l*NH*13*13, att);
        }
        {
            dim3 grid(TOKENS/64, 128/64);
            gemm_tc_kernel<<<grid, 256, GEMM_SMEM>>>(att, wp + l*128*128, proj_b + l*128,
                                                     y, 128, 0);
        }
    }

    ln_out_kernel<<<TOKENS/32, 256>>>(y, ln_g, ln_b, out);
}